// round 8
// baseline (speedup 1.0000x reference)
#include <cuda_runtime.h>
#include <math.h>

// ---------------- problem constants ----------------
#define BB 8
#define SS 1024
#define DD 512
#define HH 256
#define NSLOT 64
#define SDIM 128
#define NHEAD 4
#define DHEAD 64
#define TOK (BB*SS)

#define INV_SCALE 0.08838834764831845f  // 1/sqrt(128)

// ---------------- scratch (device globals; no allocations allowed) ----------------
__device__ float g_q   [TOK*SDIM];
__device__ float g_wr  [TOK*SDIM];
__device__ float g_xh0 [TOK*HH];
__device__ float g_bq  [TOK*SDIM];
__device__ float g_ba  [TOK*NSLOT];
__device__ float g_read[TOK*SDIM];
__device__ float g_xh  [TOK*HH];
__device__ float g_ypre[TOK*DD];
__device__ float g_lnx [TOK*DD];

__device__ __forceinline__ float sigmoidf_(float x) { return 1.f / (1.f + expf(-x)); }

// ============================================================================
// Generic tiled GEMM: C[M,N] = A[M,K] @ B[K,N] + bias[N] (+C if accum)
// M%64==0, N%64==0, K%16==0. 256 threads, 64x64 tile, 4x4 microtile.
// ============================================================================
__global__ void __launch_bounds__(256) gemm_bias(
    const float* __restrict__ A, const float* __restrict__ Bm,
    const float* __restrict__ bias, float* __restrict__ C,
    int M, int Nc, int K, int accum)
{
    __shared__ float As[16][68];
    __shared__ float Bs[16][68];
    const int tid = threadIdx.x;
    const int tc = tid & 15, tr = tid >> 4;
    const int row0 = blockIdx.y * 64, col0 = blockIdx.x * 64;

    const int am  = tid >> 2;          // 0..63
    const int ak4 = (tid & 3) << 2;    // 0,4,8,12
    const int bk  = tid >> 4;          // 0..15
    const int bn4 = (tid & 15) << 2;   // 0..60

    float acc[4][4];
#pragma unroll
    for (int i = 0; i < 4; i++)
#pragma unroll
        for (int j = 0; j < 4; j++) acc[i][j] = 0.f;

    for (int k0 = 0; k0 < K; k0 += 16) {
        float4 av = *(const float4*)(A + (size_t)(row0 + am) * K + k0 + ak4);
        As[ak4 + 0][am] = av.x; As[ak4 + 1][am] = av.y;
        As[ak4 + 2][am] = av.z; As[ak4 + 3][am] = av.w;
        float4 bv = *(const float4*)(Bm + (size_t)(k0 + bk) * Nc + col0 + bn4);
        *(float4*)&Bs[bk][bn4] = bv;
        __syncthreads();
#pragma unroll
        for (int k = 0; k < 16; k++) {
            float4 a4 = *(const float4*)&As[k][tr << 2];
            float4 b4 = *(const float4*)&Bs[k][tc << 2];
            float ar[4] = {a4.x, a4.y, a4.z, a4.w};
            float br[4] = {b4.x, b4.y, b4.z, b4.w};
#pragma unroll
            for (int i = 0; i < 4; i++)
#pragma unroll
                for (int j = 0; j < 4; j++) acc[i][j] += ar[i] * br[j];
        }
        __syncthreads();
    }
    const float4 bv4 = *(const float4*)(bias + col0 + (tc << 2));
    const float bb4[4] = {bv4.x, bv4.y, bv4.z, bv4.w};
#pragma unroll
    for (int i = 0; i < 4; i++) {
        float* cp = C + (size_t)(row0 + (tr << 2) + i) * Nc + col0 + (tc << 2);
#pragma unroll
        for (int j = 0; j < 4; j++) {
            float v = acc[i][j] + bb4[j];
            if (accum) v += cp[j];
            cp[j] = v;
        }
    }
}

// ============================================================================
// ba = softmax(bq @ keys^T / sqrt(SD)). One block (64 thr) per token.
// ============================================================================
__global__ void __launch_bounds__(64) ba_kernel(
    const float* __restrict__ bq, const float* __restrict__ keys,
    float* __restrict__ ba)
{
    __shared__ float redm[2];
    __shared__ float reds[2];
    const int t = blockIdx.x;
    const int n = threadIdx.x;
    const float* qv = bq + (size_t)t * SDIM;
    const float* kr = keys + (size_t)n * SDIM;
    float s = 0.f;
#pragma unroll 8
    for (int d = 0; d < SDIM; d++) s += qv[d] * kr[d];
    s *= INV_SCALE;
    float m = s;
#pragma unroll
    for (int o = 16; o; o >>= 1) m = fmaxf(m, __shfl_xor_sync(0xffffffffu, m, o));
    if ((n & 31) == 0) redm[n >> 5] = m;
    __syncthreads();
    float gm = fmaxf(redm[0], redm[1]);
    float e = expf(s - gm);
    float se = e;
#pragma unroll
    for (int o = 16; o; o >>= 1) se += __shfl_xor_sync(0xffffffffu, se, o);
    if ((n & 31) == 0) reds[n >> 5] = se;
    __syncthreads();
    float tot = reds[0] + reds[1];
    ba[(size_t)t * NSLOT + n] = e / tot;
}

// ============================================================================
// LayerNorm over D=512 per token. One block (256 thr) per token.
// ============================================================================
__global__ void __launch_bounds__(256) ln512_kernel(
    const float* __restrict__ X, const float* __restrict__ gg,
    const float* __restrict__ bbv, float* __restrict__ Y)
{
    __shared__ float rs[18];
    const int t = blockIdx.x;
    const int i = threadIdx.x;
    const float* x = X + (size_t)t * DD;
    float v0 = x[i], v1 = x[i + 256];
    float s = v0 + v1, s2 = v0 * v0 + v1 * v1;
#pragma unroll
    for (int o = 16; o; o >>= 1) {
        s  += __shfl_xor_sync(0xffffffffu, s, o);
        s2 += __shfl_xor_sync(0xffffffffu, s2, o);
    }
    if ((i & 31) == 0) { rs[i >> 5] = s; rs[8 + (i >> 5)] = s2; }
    __syncthreads();
    if (i == 0) {
        float a = 0.f, b2 = 0.f;
#pragma unroll
        for (int k = 0; k < 8; k++) { a += rs[k]; b2 += rs[8 + k]; }
        float mean = a / (float)DD;
        float var = b2 / (float)DD - mean * mean;
        rs[16] = mean;
        rs[17] = rsqrtf(var + 1e-5f);
    }
    __syncthreads();
    float mean = rs[16], rstd = rs[17];
    Y[(size_t)t * DD + i]       = (v0 - mean) * rstd * gg[i]       + bbv[i];
    Y[(size_t)t * DD + i + 256] = (v1 - mean) * rstd * gg[i + 256] + bbv[i + 256];
}

// ============================================================================
// Sequential recurrence: 8 CTAs (one per batch) x 1024 threads.
// Slots + bp_w in SMEM; DeltaNet state S in registers (32 floats/thread).
// ============================================================================
struct SeqSmem {
    float slots[NSLOT][SDIM];   // 32 KB
    float bpw[SDIM*HH];         // 131 KB: bp_w resident for the whole scan
    float ws[4096];
    float q[SDIM];
    float wr[SDIM];
    float scores[NSLOT];
    float a[NSLOT];
    float ga[NSLOT];
    float ba[NSLOT];
    float g2[NSLOT];
    float bind[SDIM];
    float xh[HH];
    float qkv[3*HH];
    float khn[HH];
    float knormh[NHEAD];
    float beta[NHEAD];
    float ovec[HH];
    float pre[HH];
    float proj[SDIM];
    float red2[4];
    // cached per-step constants
    float c_bp_b[HH];
    float c_bqkv[2][3*HH];
    float c_wbeta[2][HH*NHEAD];
    float c_bbeta[2][4];
    float c_bo[2][HH];
    float c_lng[2][HH];
    float c_lnb[2][HH];
    float c_supb[SDIM];
};

__global__ void __launch_bounds__(1024, 1) seq_kernel(
    const float* __restrict__ sb_init,
    const float* __restrict__ bp_w,    const float* __restrict__ bp_b,
    const float* __restrict__ dn_wqkv, const float* __restrict__ dn_bqkv,
    const float* __restrict__ dn_wbeta,const float* __restrict__ dn_bbeta,
    const float* __restrict__ dn_wo,   const float* __restrict__ dn_bo,
    const float* __restrict__ dn_lng,  const float* __restrict__ dn_lnb,
    const float* __restrict__ sup_w,   const float* __restrict__ sup_b)
{
    extern __shared__ float smem_raw[];
    SeqSmem& s = *reinterpret_cast<SeqSmem*>(smem_raw);
    const int tid = threadIdx.x;
    const int b = blockIdx.x;

    // ---- init: slots = sb_init (same for every batch), cache constants ----
    for (int i = tid; i < NSLOT*SDIM/4; i += 1024)
        ((float4*)s.slots)[i] = ((const float4*)sb_init)[i];
    // bp_w resident copy (131 KB)
    for (int i = tid; i < SDIM*HH/4; i += 1024)
        ((float4*)s.bpw)[i] = ((const float4*)bp_w)[i];
    for (int i = tid; i < HH; i += 1024)      s.c_bp_b[i] = bp_b[i];
    for (int i = tid; i < 2*3*HH; i += 1024)  (&s.c_bqkv[0][0])[i] = dn_bqkv[i];
    for (int i = tid; i < 2*HH*NHEAD; i += 1024) (&s.c_wbeta[0][0])[i] = dn_wbeta[i];
    for (int i = tid; i < 8; i += 1024)       (&s.c_bbeta[0][0])[i] = dn_bbeta[i];
    for (int i = tid; i < 2*HH; i += 1024) {
        (&s.c_bo[0][0])[i]  = dn_bo[i];
        (&s.c_lng[0][0])[i] = dn_lng[i];
        (&s.c_lnb[0][0])[i] = dn_lnb[i];
    }
    for (int i = tid; i < SDIM; i += 1024)    s.c_supb[i] = sup_b[i];

    // register-resident DeltaNet state: thread (r = tid>>2, p = tid&3)
    // owns S[l][h][i_row][p*16 .. p*16+16), h = r>>6, i_row = r&63
    float4 S0[4], S1[4];
#pragma unroll
    for (int g = 0; g < 4; g++) {
        S0[g] = make_float4(0.f,0.f,0.f,0.f);
        S1[g] = make_float4(0.f,0.f,0.f,0.f);
    }
    const int r_row = tid >> 2, part = tid & 3;
    const int hh_r = r_row >> 6;

    // ---- prefetch token-0 per-token vectors into registers ----
    float4 pv = make_float4(0.f,0.f,0.f,0.f);
    {
        const size_t idx0 = (size_t)b * SS;
        if (tid < 32)       pv = ((const float4*)(g_q  + idx0*SDIM))[tid];
        else if (tid < 64)  pv = ((const float4*)(g_wr + idx0*SDIM))[tid-32];
        else if (tid < 80)  pv = ((const float4*)(g_ba + idx0*NSLOT))[tid-64];
    }

    for (int t = 0; t < SS; ++t) {
        const size_t idx = (size_t)b * SS + t;

        // ---- commit prefetched per-token vectors to SMEM ----
        if (tid < 32)       ((float4*)s.q )[tid]    = pv;
        else if (tid < 64)  ((float4*)s.wr)[tid-32] = pv;
        else if (tid < 80)  ((float4*)s.ba)[tid-64] = pv;
        __syncthreads();

        // early xh0 load: consumed only in Stage D, latency hides behind A+B
        float xh0_reg = 0.f;
        if (tid < 256) xh0_reg = g_xh0[idx*HH + tid];

        // ---- Stage A: slot attention scores ----
        {
            const int slot = tid >> 4, l16 = tid & 15;
            float4 sv = *(const float4*)&s.slots[slot][l16*4];
            float4 qv = *(const float4*)&s.q[l16*4];
            float acc = sv.x*qv.x + sv.y*qv.y + sv.z*qv.z + sv.w*qv.w;
            float4 sv2 = *(const float4*)&s.slots[slot][64 + l16*4];
            float4 qv2 = *(const float4*)&s.q[64 + l16*4];
            acc += sv2.x*qv2.x + sv2.y*qv2.y + sv2.z*qv2.z + sv2.w*qv2.w;
            acc += __shfl_xor_sync(0xffffffffu, acc, 1);
            acc += __shfl_xor_sync(0xffffffffu, acc, 2);
            acc += __shfl_xor_sync(0xffffffffu, acc, 4);
            acc += __shfl_xor_sync(0xffffffffu, acc, 8);
            if (l16 == 0) s.scores[slot] = acc * INV_SCALE;
        }
        __syncthreads();
        // softmax + gates
        if (tid < 32) {
            float s0 = s.scores[tid], s1 = s.scores[tid+32];
            float m = fmaxf(s0, s1);
#pragma unroll
            for (int o = 16; o; o >>= 1) m = fmaxf(m, __shfl_xor_sync(0xffffffffu, m, o));
            float e0 = expf(s0 - m), e1 = expf(s1 - m);
            float sum = e0 + e1;
#pragma unroll
            for (int o = 16; o; o >>= 1) sum += __shfl_xor_sync(0xffffffffu, sum, o);
            float inv = 1.f / sum;
            float a0 = e0 * inv, a1 = e1 * inv;
            s.a[tid] = a0;        s.a[tid+32] = a1;
            s.ga[tid] = sigmoidf_(a0); s.ga[tid+32] = sigmoidf_(a1);
        } else if (tid < 64) {
            int w = tid - 32;
            s.g2[w]    = sigmoidf_(s.ba[w]);
            s.g2[w+32] = sigmoidf_(s.ba[w+32]);
        }
        __syncthreads();

        // ---- Stage B: read (old slots), gated write, bindings (new slots) ----
        {
            const int col = tid & 127, grp = tid >> 7;
            float pr = 0.f, pb = 0.f;
            const float wrc = s.wr[col];
#pragma unroll
            for (int k = 0; k < 8; ++k) {
                const int n = grp*8 + k;
                const float an = s.a[n], gn = s.ga[n], ban = s.ba[n];
                float oldv = s.slots[n][col];
                pr += an * oldv;
                float nv = oldv + gn * (an * wrc - oldv);
                s.slots[n][col] = nv;
                pb += ban * nv;
            }
            s.ws[grp*128 + col]        = pr;
            s.ws[1024 + grp*128 + col] = pb;
        }
        __syncthreads();
        if (tid < 128) {
            float rr = 0.f, bb2 = 0.f;
#pragma unroll
            for (int k = 0; k < 8; ++k) {
                rr  += s.ws[k*128 + tid];
                bb2 += s.ws[1024 + k*128 + tid];
            }
            g_read[idx*SDIM + tid] = rr;
            s.bind[tid] = bb2;
        }
        __syncthreads();

        // ---- Stage D: xh = xh0 + bind @ bp_w + bp_b (bp_w from SMEM) ----
        {
            const int cg = tid & 63, ks = tid >> 6;
            const float4* W = (const float4*)s.bpw;
            float4 acc = make_float4(0.f,0.f,0.f,0.f);
#pragma unroll
            for (int k = 0; k < 8; ++k) {
                const int i = ks*8 + k;
                const float bi = s.bind[i];
                const float4 w = W[i*64 + cg];
                acc.x += bi*w.x; acc.y += bi*w.y; acc.z += bi*w.z; acc.w += bi*w.w;
            }
            *(float4*)&s.ws[ks*256 + cg*4] = acc;
        }
        __syncthreads();
        if (tid < 256) {
            float v = xh0_reg + s.c_bp_b[tid];
#pragma unroll
            for (int k = 0; k < 16; ++k) v += s.ws[k*256 + tid];
            s.xh[tid] = v;
        }
        __syncthreads();

        // ---- DeltaNet layers ----
#pragma unroll
        for (int l = 0; l < 2; ++l) {
            // qkv = xh @ Wqkv + b (768 threads); beta projection on idle threads
            if (tid < 768) {
                const int jg = tid % 192, ks = tid / 192;
                const float4* W = (const float4*)(dn_wqkv + (size_t)l*HH*3*HH);
                float4 acc = make_float4(0.f,0.f,0.f,0.f);
#pragma unroll 8
                for (int k = 0; k < 64; ++k) {
                    const int i = ks*64 + k;
                    const float xv = s.xh[i];
                    const float4 w = W[i*192 + jg];
                    acc.x += xv*w.x; acc.y += xv*w.y; acc.z += xv*w.z; acc.w += xv*w.w;
                }
                *(float4*)&s.ws[ks*768 + jg*4] = acc;
            } else if (tid < 896) {
                // beta = sigmoid(xh @ wbeta + b): depends only on xh, runs here
                const int hh = (tid - 768) >> 5, w = tid & 31;
                float bp = 0.f;
#pragma unroll
                for (int e = 0; e < 8; ++e) {
                    const int i = e*32 + w;
                    bp += s.xh[i] * (&s.c_wbeta[0][0])[l*1024 + i*4 + hh];
                }
#pragma unroll
                for (int o = 16; o; o >>= 1)
                    bp += __shfl_xor_sync(0xffffffffu, bp, o);
                if (w == 0)
                    s.beta[hh] = sigmoidf_(bp + (&s.c_bbeta[0][0])[l*4 + hh]);
            }
            __syncthreads();
            if (tid < 768) {
                float v = (&s.c_bqkv[0][0])[l*768 + tid];
#pragma unroll
                for (int k = 0; k < 4; ++k) v += s.ws[k*768 + tid];
                s.qkv[tid] = v;
            }
            __syncthreads();
            // k-norm (one warp per head)
            if (tid < 128) {
                const int hh = tid >> 5, w = tid & 31;
                float k0 = s.qkv[256 + hh*64 + w];
                float k1 = s.qkv[256 + hh*64 + 32 + w];
                float ssq = k0*k0 + k1*k1;
#pragma unroll
                for (int o = 16; o; o >>= 1)
                    ssq += __shfl_xor_sync(0xffffffffu, ssq, o);
                if (w == 0) s.knormh[hh] = 1.f / (sqrtf(ssq) + 1e-6f);
            }
            __syncthreads();
            if (tid < 256) s.khn[tid] = s.qkv[256 + tid] * s.knormh[tid >> 6];
            __syncthreads();
            // state update + o (S in registers)
            {
                float4* Sreg = (l == 0) ? S0 : S1;
                const float betah = s.beta[hh_r];
                const int kb = hh_r*64 + part*16;
                float sk = 0.f;
#pragma unroll
                for (int g = 0; g < 4; ++g) {
                    const float4 kk = *(const float4*)&s.khn[kb + g*4];
                    sk += Sreg[g].x*kk.x + Sreg[g].y*kk.y + Sreg[g].z*kk.z + Sreg[g].w*kk.w;
                }
                sk += __shfl_xor_sync(0xffffffffu, sk, 1);
                sk += __shfl_xor_sync(0xffffffffu, sk, 2);
                const float vh = s.qkv[512 + r_row];
                const float delta = betah * (vh - sk);
                float op = 0.f;
#pragma unroll
                for (int g = 0; g < 4; ++g) {
                    const float4 kk = *(const float4*)&s.khn[kb + g*4];
                    const float4 qq = *(const float4*)&s.qkv[kb + g*4];
                    Sreg[g].x += delta*kk.x; Sreg[g].y += delta*kk.y;
                    Sreg[g].z += delta*kk.z; Sreg[g].w += delta*kk.w;
                    op += Sreg[g].x*qq.x + Sreg[g].y*qq.y + Sreg[g].z*qq.z + Sreg[g].w*qq.w;
                }
                op += __shfl_xor_sync(0xffffffffu, op, 1);
                op += __shfl_xor_sync(0xffffffffu, op, 2);
                if (part == 0) s.ovec[r_row] = op;
            }
            __syncthreads();
            // pre = xh + o @ dn_wo + bo ; xh = LN(pre)
            {
                const int cg = tid & 63, ks = tid >> 6;
                const float4* W = (const float4*)(dn_wo + (size_t)l*HH*HH);
                float4 acc = make_float4(0.f,0.f,0.f,0.f);
#pragma unroll 4
                for (int k = 0; k < 16; ++k) {
                    const int i = ks*16 + k;
                    const float ov = s.ovec[i];
                    const float4 w = W[i*64 + cg];
                    acc.x += ov*w.x; acc.y += ov*w.y; acc.z += ov*w.z; acc.w += ov*w.w;
                }
                *(float4*)&s.ws[ks*256 + cg*4] = acc;
            }
            __syncthreads();
            if (tid < 256) {
                float v = s.xh[tid] + (&s.c_bo[0][0])[l*256 + tid];
#pragma unroll
                for (int k = 0; k < 16; ++k) v += s.ws[k*256 + tid];
                s.pre[tid] = v;
            }
            __syncthreads();
            if (tid < 32) {
                float sum = 0.f, sq = 0.f;
#pragma unroll
                for (int e = 0; e < 8; ++e) {
                    const float v = s.pre[tid + 32*e];
                    sum += v; sq += v*v;
                }
#pragma unroll
                for (int o = 16; o; o >>= 1) {
                    sum += __shfl_xor_sync(0xffffffffu, sum, o);
                    sq  += __shfl_xor_sync(0xffffffffu, sq,  o);
                }
                if (tid == 0) {
                    const float mean = sum * (1.f/256.f);
                    const float var  = sq * (1.f/256.f) - mean*mean;
                    s.red2[0] = mean;
                    s.red2[1] = rsqrtf(var + 1e-5f);
                }
            }
            __syncthreads();
            if (tid < 256) {
                s.xh[tid] = (s.pre[tid] - s.red2[0]) * s.red2[1]
                          * (&s.c_lng[0][0])[l*256 + tid] + (&s.c_lnb[0][0])[l*256 + tid];
            }
            __syncthreads();
        }

        // ---- sup projection: proj = xh @ sup_w ----
        {
            const int cg = tid & 31, ks = tid >> 5;
            const float4* W = (const float4*)sup_w;
            float4 acc = make_float4(0.f,0.f,0.f,0.f);
#pragma unroll
            for (int k = 0; k < 8; ++k) {
                const int i = ks*8 + k;
                const float xv = s.xh[i];
                const float4 w = W[i*32 + cg];
                acc.x += xv*w.x; acc.y += xv*w.y; acc.z += xv*w.z; acc.w += xv*w.w;
            }
            *(float4*)&s.ws[ks*128 + cg*4] = acc;
        }
        __syncthreads();
        if (tid < 128) {
            float v = 0.f;
#pragma unroll
            for (int k = 0; k < 32; ++k) v += s.ws[k*128 + tid];
            s.proj[tid] = v;
        } else if (tid >= 256 && tid < 512) {
            g_xh[idx*HH + (tid - 256)] = s.xh[tid - 256];
        }
        __syncthreads();

        // ---- prefetch next token's vectors (overlaps final slot write) ----
        if (t + 1 < SS) {
            const size_t idx1 = idx + 1;
            if (tid < 32)       pv = ((const float4*)(g_q  + idx1*SDIM))[tid];
            else if (tid < 64)  pv = ((const float4*)(g_wr + idx1*SDIM))[tid-32];
            else if (tid < 80)  pv = ((const float4*)(g_ba + idx1*NSLOT))[tid-64];
        }

        // ---- second gated slot write ----
        {
            const int col = tid & 127, grp = tid >> 7;
            const float pvv = s.proj[col], sbv = s.c_supb[col];
#pragma unroll
            for (int k = 0; k < 8; ++k) {
                const int n = grp*8 + k;
                const float gn = s.g2[n];
                const float sv = s.ba[n]*pvv + sbv;
                const float oldv = s.slots[n][col];
                s.slots[n][col] = oldv + gn*(sv - oldv);
            }
        }
        __syncthreads();
    }
}

// ============================================================================
extern "C" void kernel_launch(void* const* d_in, const int* in_sizes, int n_in,
                              void* d_out, int out_size) {
    (void)in_sizes; (void)n_in; (void)out_size;
    const float* x        = (const float*)d_in[0];
    const float* sb_init  = (const float*)d_in[1];
    const float* sb_wq    = (const float*)d_in[2];
    const float* sb_bq    = (const float*)d_in[3];
    const float* sb_ww    = (const float*)d_in[4];
    const float* sb_bw    = (const float*)d_in[5];
    const float* sb_wo    = (const float*)d_in[6];
    const float* sb_bo    = (const float*)d_in[7];
    const float* p_win    = (const float*)d_in[8];
    const float* p_bin    = (const float*)d_in[9];
    const float* b_wq     = (const float*)d_in[10];
    const float* b_bq     = (const float*)d_in[11];
    const float* b_keys   = (const float*)d_in[12];
    const float* bp_w     = (const float*)d_in[13];
    const float* bp_b     = (const float*)d_in[14];
    const float* dn_wqkv  = (const float*)d_in[15];
    const float* dn_bqkv  = (const float*)d_in[16];
    const float* dn_wbeta = (const float*)d_in[17];
    const float* dn_bbeta = (const float*)d_in[18];
    const float* dn_wo    = (const float*)d_in[19];
    const float* dn_bo    = (const float*)d_in[20];
    const float* dn_lng   = (const float*)d_in[21];
    const float* dn_lnb   = (const float*)d_in[22];
    const float* sup_w    = (const float*)d_in[23];
    const float* sup_b    = (const float*)d_in[24];
    const float* op_w     = (const float*)d_in[25];
    const float* op_b     = (const float*)d_in[26];
    const float* oln_g    = (const float*)d_in[27];
    const float* oln_b    = (const float*)d_in[28];
    const float* ow       = (const float*)d_in[29];
    const float* ob       = (const float*)d_in[30];
    float* out = (float*)d_out;

    float *gq, *gwr, *gxh0, *gbq, *gba, *gread, *gxh, *gypre, *glnx;
    cudaGetSymbolAddress((void**)&gq,    g_q);
    cudaGetSymbolAddress((void**)&gwr,   g_wr);
    cudaGetSymbolAddress((void**)&gxh0,  g_xh0);
    cudaGetSymbolAddress((void**)&gbq,   g_bq);
    cudaGetSymbolAddress((void**)&gba,   g_ba);
    cudaGetSymbolAddress((void**)&gread, g_read);
    cudaGetSymbolAddress((void**)&gxh,   g_xh);
    cudaGetSymbolAddress((void**)&gypre, g_ypre);
    cudaGetSymbolAddress((void**)&glnx,  g_lnx);

    const int seq_smem = (int)sizeof(SeqSmem);
    cudaFuncSetAttribute(seq_kernel, cudaFuncAttributeMaxDynamicSharedMemorySize, seq_smem);

    dim3 blk(256);
    // precompute phase
    gemm_bias<<<dim3(SDIM/64, TOK/64), blk>>>(x, sb_wq, sb_bq, gq,   TOK, SDIM, DD, 0);
    gemm_bias<<<dim3(SDIM/64, TOK/64), blk>>>(x, sb_ww, sb_bw, gwr,  TOK, SDIM, DD, 0);
    gemm_bias<<<dim3(HH/64,   TOK/64), blk>>>(x, p_win, p_bin, gxh0, TOK, HH,   DD, 0);
    gemm_bias<<<dim3(SDIM/64, TOK/64), blk>>>(gxh0, b_wq, b_bq, gbq, TOK, SDIM, HH, 0);
    ba_kernel<<<TOK, 64>>>(gbq, b_keys, gba);

    // sequential core
    seq_kernel<<<BB, 1024, seq_smem>>>(sb_init, bp_w, bp_b,
                                       dn_wqkv, dn_bqkv, dn_wbeta, dn_bbeta,
                                       dn_wo, dn_bo, dn_lng, dn_lnb,
                                       sup_w, sup_b);

    // deferred output projections
    gemm_bias<<<dim3(DD/64, TOK/64), blk>>>(gread, sb_wo, sb_bo, gypre, TOK, DD, SDIM, 0);
    gemm_bias<<<dim3(DD/64, TOK/64), blk>>>(gxh,   op_w,  op_b,  gypre, TOK, DD, HH,   1);
    ln512_kernel<<<TOK, 256>>>(gypre, oln_g, oln_b, glnx);
    gemm_bias<<<dim3(DD/64, TOK/64), blk>>>(glnx, ow, ob, out, TOK, DD, DD, 0);
}

// round 14
// speedup vs baseline: 1.0075x; 1.0075x over previous
#include <cuda_runtime.h>
#include <math.h>

// ---------------- problem constants ----------------
#define BB 8
#define SS 1024
#define DD 512
#define HH 256
#define NSLOT 64
#define SDIM 128
#define NHEAD 4
#define DHEAD 64
#define TOK (BB*SS)

#define INV_SCALE 0.08838834764831845f  // 1/sqrt(128)

// ---------------- scratch (device globals; no allocations allowed) ----------------
__device__ float g_q   [TOK*SDIM];
__device__ float g_wr  [TOK*SDIM];
__device__ float g_xh0 [TOK*HH];
__device__ float g_bq  [TOK*SDIM];
__device__ float g_ba  [TOK*NSLOT];
__device__ float g_read[TOK*SDIM];
__device__ float g_xh  [TOK*HH];
__device__ float g_ypre[TOK*DD];
__device__ float g_lnx [TOK*DD];

__device__ __forceinline__ float sigmoidf_(float x) { return 1.f / (1.f + expf(-x)); }

// ---- packed fp32x2 FMA helpers (sm_103a; ptxas never auto-fuses these) ----
__device__ __forceinline__ void fma_f32x2(unsigned long long& acc,
                                          unsigned long long a,
                                          unsigned long long b) {
    asm("fma.rn.f32x2 %0, %1, %2, %3;" : "=l"(acc) : "l"(a), "l"(b), "l"(acc));
}
__device__ __forceinline__ unsigned long long bcast_f32x2(float x) {
    unsigned long long r;
    asm("mov.b64 %0, {%1, %1};" : "=l"(r) : "f"(x));
    return r;
}

// ============================================================================
// Generic tiled GEMM: C[M,N] = A[M,K] @ B[K,N] + bias[N] (+C if accum)
// ============================================================================
__global__ void __launch_bounds__(256) gemm_bias(
    const float* __restrict__ A, const float* __restrict__ Bm,
    const float* __restrict__ bias, float* __restrict__ C,
    int M, int Nc, int K, int accum)
{
    __shared__ float As[16][68];
    __shared__ float Bs[16][68];
    const int tid = threadIdx.x;
    const int tc = tid & 15, tr = tid >> 4;
    const int row0 = blockIdx.y * 64, col0 = blockIdx.x * 64;

    const int am  = tid >> 2;
    const int ak4 = (tid & 3) << 2;
    const int bk  = tid >> 4;
    const int bn4 = (tid & 15) << 2;

    float acc[4][4];
#pragma unroll
    for (int i = 0; i < 4; i++)
#pragma unroll
        for (int j = 0; j < 4; j++) acc[i][j] = 0.f;

    for (int k0 = 0; k0 < K; k0 += 16) {
        float4 av = *(const float4*)(A + (size_t)(row0 + am) * K + k0 + ak4);
        As[ak4 + 0][am] = av.x; As[ak4 + 1][am] = av.y;
        As[ak4 + 2][am] = av.z; As[ak4 + 3][am] = av.w;
        float4 bv = *(const float4*)(Bm + (size_t)(k0 + bk) * Nc + col0 + bn4);
        *(float4*)&Bs[bk][bn4] = bv;
        __syncthreads();
#pragma unroll
        for (int k = 0; k < 16; k++) {
            float4 a4 = *(const float4*)&As[k][tr << 2];
            float4 b4 = *(const float4*)&Bs[k][tc << 2];
            float ar[4] = {a4.x, a4.y, a4.z, a4.w};
            float br[4] = {b4.x, b4.y, b4.z, b4.w};
#pragma unroll
            for (int i = 0; i < 4; i++)
#pragma unroll
                for (int j = 0; j < 4; j++) acc[i][j] += ar[i] * br[j];
        }
        __syncthreads();
    }
    const float4 bv4 = *(const float4*)(bias + col0 + (tc << 2));
    const float bb4[4] = {bv4.x, bv4.y, bv4.z, bv4.w};
#pragma unroll
    for (int i = 0; i < 4; i++) {
        float* cp = C + (size_t)(row0 + (tr << 2) + i) * Nc + col0 + (tc << 2);
#pragma unroll
        for (int j = 0; j < 4; j++) {
            float v = acc[i][j] + bb4[j];
            if (accum) v += cp[j];
            cp[j] = v;
        }
    }
}

// ============================================================================
// ba = softmax(bq @ keys^T / sqrt(SD)). One block (64 thr) per token.
// ============================================================================
__global__ void __launch_bounds__(64) ba_kernel(
    const float* __restrict__ bq, const float* __restrict__ keys,
    float* __restrict__ ba)
{
    __shared__ float redm[2];
    __shared__ float reds[2];
    const int t = blockIdx.x;
    const int n = threadIdx.x;
    const float* qv = bq + (size_t)t * SDIM;
    const float* kr = keys + (size_t)n * SDIM;
    float s = 0.f;
#pragma unroll 8
    for (int d = 0; d < SDIM; d++) s += qv[d] * kr[d];
    s *= INV_SCALE;
    float m = s;
#pragma unroll
    for (int o = 16; o; o >>= 1) m = fmaxf(m, __shfl_xor_sync(0xffffffffu, m, o));
    if ((n & 31) == 0) redm[n >> 5] = m;
    __syncthreads();
    float gm = fmaxf(redm[0], redm[1]);
    float e = expf(s - gm);
    float se = e;
#pragma unroll
    for (int o = 16; o; o >>= 1) se += __shfl_xor_sync(0xffffffffu, se, o);
    if ((n & 31) == 0) reds[n >> 5] = se;
    __syncthreads();
    float tot = reds[0] + reds[1];
    ba[(size_t)t * NSLOT + n] = e / tot;
}

// ============================================================================
// LayerNorm over D=512 per token. One block (256 thr) per token.
// ============================================================================
__global__ void __launch_bounds__(256) ln512_kernel(
    const float* __restrict__ X, const float* __restrict__ gg,
    const float* __restrict__ bbv, float* __restrict__ Y)
{
    __shared__ float rs[18];
    const int t = blockIdx.x;
    const int i = threadIdx.x;
    const float* x = X + (size_t)t * DD;
    float v0 = x[i], v1 = x[i + 256];
    float s = v0 + v1, s2 = v0 * v0 + v1 * v1;
#pragma unroll
    for (int o = 16; o; o >>= 1) {
        s  += __shfl_xor_sync(0xffffffffu, s, o);
        s2 += __shfl_xor_sync(0xffffffffu, s2, o);
    }
    if ((i & 31) == 0) { rs[i >> 5] = s; rs[8 + (i >> 5)] = s2; }
    __syncthreads();
    if (i == 0) {
        float a = 0.f, b2 = 0.f;
#pragma unroll
        for (int k = 0; k < 8; k++) { a += rs[k]; b2 += rs[8 + k]; }
        float mean = a / (float)DD;
        float var = b2 / (float)DD - mean * mean;
        rs[16] = mean;
        rs[17] = rsqrtf(var + 1e-5f);
    }
    __syncthreads();
    float mean = rs[16], rstd = rs[17];
    Y[(size_t)t * DD + i]       = (v0 - mean) * rstd * gg[i]       + bbv[i];
    Y[(size_t)t * DD + i + 256] = (v1 - mean) * rstd * gg[i + 256] + bbv[i + 256];
}

// ============================================================================
// Sequential recurrence: 8 CTAs (one per batch) x 1024 threads.
// Slots + bp_w in SMEM; DeltaNet state S in registers (32 floats/thread).
// f32x2-packed FMAs in all matvecs; k-norm fused into qkv reduce.
// ============================================================================
struct SeqSmem {
    float slots[NSLOT][SDIM];   // 32 KB
    float bpw[SDIM*HH];         // 131 KB
    float ws[4096];
    float q[SDIM];
    float wr[SDIM];
    float scores[NSLOT];
    float a[NSLOT];
    float ga[NSLOT];
    float ba[NSLOT];
    float g2[NSLOT];
    float bind[SDIM];
    float xh[HH];
    float qkv[3*HH];
    float kssq[8];              // per-k-warp sum-of-squares partials
    float beta[NHEAD];
    float ovec[HH];
    float pre[HH];
    float proj[SDIM];
    float red2[4];
    // cached per-step constants
    float c_bp_b[HH];
    float c_bqkv[2][3*HH];
    float c_wbeta[2][HH*NHEAD];
    float c_bbeta[2][4];
    float c_bo[2][HH];
    float c_lng[2][HH];
    float c_lnb[2][HH];
    float c_supb[SDIM];
};

__global__ void __launch_bounds__(1024, 1) seq_kernel(
    const float* __restrict__ sb_init,
    const float* __restrict__ bp_w,    const float* __restrict__ bp_b,
    const float* __restrict__ dn_wqkv, const float* __restrict__ dn_bqkv,
    const float* __restrict__ dn_wbeta,const float* __restrict__ dn_bbeta,
    const float* __restrict__ dn_wo,   const float* __restrict__ dn_bo,
    const float* __restrict__ dn_lng,  const float* __restrict__ dn_lnb,
    const float* __restrict__ sup_w,   const float* __restrict__ sup_b)
{
    extern __shared__ float smem_raw[];
    SeqSmem& s = *reinterpret_cast<SeqSmem*>(smem_raw);
    const int tid = threadIdx.x;
    const int b = blockIdx.x;

    // ---- init ----
    for (int i = tid; i < NSLOT*SDIM/4; i += 1024)
        ((float4*)s.slots)[i] = ((const float4*)sb_init)[i];
    for (int i = tid; i < SDIM*HH/4; i += 1024)
        ((float4*)s.bpw)[i] = ((const float4*)bp_w)[i];
    for (int i = tid; i < HH; i += 1024)      s.c_bp_b[i] = bp_b[i];
    for (int i = tid; i < 2*3*HH; i += 1024)  (&s.c_bqkv[0][0])[i] = dn_bqkv[i];
    for (int i = tid; i < 2*HH*NHEAD; i += 1024) (&s.c_wbeta[0][0])[i] = dn_wbeta[i];
    for (int i = tid; i < 8; i += 1024)       (&s.c_bbeta[0][0])[i] = dn_bbeta[i];
    for (int i = tid; i < 2*HH; i += 1024) {
        (&s.c_bo[0][0])[i]  = dn_bo[i];
        (&s.c_lng[0][0])[i] = dn_lng[i];
        (&s.c_lnb[0][0])[i] = dn_lnb[i];
    }
    for (int i = tid; i < SDIM; i += 1024)    s.c_supb[i] = sup_b[i];

    // register-resident DeltaNet state: thread (r = tid>>2, p = tid&3)
    float4 S0[4], S1[4];
#pragma unroll
    for (int g = 0; g < 4; g++) {
        S0[g] = make_float4(0.f,0.f,0.f,0.f);
        S1[g] = make_float4(0.f,0.f,0.f,0.f);
    }
    const int r_row = tid >> 2, part = tid & 3;
    const int hh_r = r_row >> 6;

    // ---- prefetch token-0 per-token vectors ----
    float4 pv = make_float4(0.f,0.f,0.f,0.f);
    {
        const size_t idx0 = (size_t)b * SS;
        if (tid < 32)       pv = ((const float4*)(g_q  + idx0*SDIM))[tid];
        else if (tid < 64)  pv = ((const float4*)(g_wr + idx0*SDIM))[tid-32];
        else if (tid < 80)  pv = ((const float4*)(g_ba + idx0*NSLOT))[tid-64];
    }

    for (int t = 0; t < SS; ++t) {
        const size_t idx = (size_t)b * SS + t;

        if (tid < 32)       ((float4*)s.q )[tid]    = pv;
        else if (tid < 64)  ((float4*)s.wr)[tid-32] = pv;
        else if (tid < 80)  ((float4*)s.ba)[tid-64] = pv;
        __syncthreads();

        float xh0_reg = 0.f;
        if (tid < 256) xh0_reg = g_xh0[idx*HH + tid];

        // ---- Stage A: slot attention scores ----
        {
            const int slot = tid >> 4, l16 = tid & 15;
            float4 sv = *(const float4*)&s.slots[slot][l16*4];
            float4 qv = *(const float4*)&s.q[l16*4];
            float acc = sv.x*qv.x + sv.y*qv.y + sv.z*qv.z + sv.w*qv.w;
            float4 sv2 = *(const float4*)&s.slots[slot][64 + l16*4];
            float4 qv2 = *(const float4*)&s.q[64 + l16*4];
            acc += sv2.x*qv2.x + sv2.y*qv2.y + sv2.z*qv2.z + sv2.w*qv2.w;
            acc += __shfl_xor_sync(0xffffffffu, acc, 1);
            acc += __shfl_xor_sync(0xffffffffu, acc, 2);
            acc += __shfl_xor_sync(0xffffffffu, acc, 4);
            acc += __shfl_xor_sync(0xffffffffu, acc, 8);
            if (l16 == 0) s.scores[slot] = acc * INV_SCALE;
        }
        __syncthreads();
        // softmax + gates
        if (tid < 32) {
            float s0 = s.scores[tid], s1 = s.scores[tid+32];
            float m = fmaxf(s0, s1);
#pragma unroll
            for (int o = 16; o; o >>= 1) m = fmaxf(m, __shfl_xor_sync(0xffffffffu, m, o));
            float e0 = expf(s0 - m), e1 = expf(s1 - m);
            float sum = e0 + e1;
#pragma unroll
            for (int o = 16; o; o >>= 1) sum += __shfl_xor_sync(0xffffffffu, sum, o);
            float inv = 1.f / sum;
            float a0 = e0 * inv, a1 = e1 * inv;
            s.a[tid] = a0;        s.a[tid+32] = a1;
            s.ga[tid] = sigmoidf_(a0); s.ga[tid+32] = sigmoidf_(a1);
        } else if (tid < 64) {
            int w = tid - 32;
            s.g2[w]    = sigmoidf_(s.ba[w]);
            s.g2[w+32] = sigmoidf_(s.ba[w+32]);
        }
        __syncthreads();

        // ---- Stage B ----
        {
            const int col = tid & 127, grp = tid >> 7;
            float pr = 0.f, pb = 0.f;
            const float wrc = s.wr[col];
#pragma unroll
            for (int k = 0; k < 8; ++k) {
                const int n = grp*8 + k;
                const float an = s.a[n], gn = s.ga[n], ban = s.ba[n];
                float oldv = s.slots[n][col];
                pr += an * oldv;
                float nv = oldv + gn * (an * wrc - oldv);
                s.slots[n][col] = nv;
                pb += ban * nv;
            }
            s.ws[grp*128 + col]        = pr;
            s.ws[1024 + grp*128 + col] = pb;
        }
        __syncthreads();
        if (tid < 128) {
            float rr = 0.f, bb2 = 0.f;
#pragma unroll
            for (int k = 0; k < 8; ++k) {
                rr  += s.ws[k*128 + tid];
                bb2 += s.ws[1024 + k*128 + tid];
            }
            g_read[idx*SDIM + tid] = rr;
            s.bind[tid] = bb2;
        }
        __syncthreads();

        // ---- Stage D: xh = xh0 + bind @ bp_w + bp_b (bp_w in SMEM, f32x2) ----
        {
            const int cg = tid & 63, ks = tid >> 6;
            const ulonglong2* W = (const ulonglong2*)s.bpw;
            unsigned long long a01 = 0ull, a23 = 0ull;
#pragma unroll
            for (int k = 0; k < 8; ++k) {
                const int i = ks*8 + k;
                const unsigned long long xv2 = bcast_f32x2(s.bind[i]);
                const ulonglong2 w = W[i*64 + cg];
                fma_f32x2(a01, xv2, w.x);
                fma_f32x2(a23, xv2, w.y);
            }
            ulonglong2 outv; outv.x = a01; outv.y = a23;
            *(ulonglong2*)&s.ws[ks*256 + cg*4] = outv;
        }
        __syncthreads();
        if (tid < 256) {
            float v = xh0_reg + s.c_bp_b[tid];
#pragma unroll
            for (int k = 0; k < 16; ++k) v += s.ws[k*256 + tid];
            s.xh[tid] = v;
        }
        __syncthreads();

        // ---- DeltaNet layers ----
#pragma unroll
        for (int l = 0; l < 2; ++l) {
            // qkv matvec (f32x2); beta projection on warps 24-27
            if (tid < 768) {
                const int jg = tid % 192, ks = tid / 192;
                const ulonglong2* W = (const ulonglong2*)(dn_wqkv + (size_t)l*HH*3*HH);
                unsigned long long a01 = 0ull, a23 = 0ull;
#pragma unroll 8
                for (int k = 0; k < 64; ++k) {
                    const int i = ks*64 + k;
                    const unsigned long long xv2 = bcast_f32x2(s.xh[i]);
                    const ulonglong2 w = W[i*192 + jg];
                    fma_f32x2(a01, xv2, w.x);
                    fma_f32x2(a23, xv2, w.y);
                }
                ulonglong2 outv; outv.x = a01; outv.y = a23;
                *(ulonglong2*)&s.ws[ks*768 + jg*4] = outv;
            } else if (tid < 896) {
                const int hh = (tid - 768) >> 5, w = tid & 31;
                float bp = 0.f;
#pragma unroll
                for (int e = 0; e < 8; ++e) {
                    const int i = e*32 + w;
                    bp += s.xh[i] * (&s.c_wbeta[0][0])[l*1024 + i*4 + hh];
                }
#pragma unroll
                for (int o = 16; o; o >>= 1)
                    bp += __shfl_xor_sync(0xffffffffu, bp, o);
                if (w == 0)
                    s.beta[hh] = sigmoidf_(bp + (&s.c_bbeta[0][0])[l*4 + hh]);
            }
            __syncthreads();
            // qkv reduce + fused k-norm sum-of-squares (warps 8-15 own k cols)
            if (tid < 768) {
                float v = (&s.c_bqkv[0][0])[l*768 + tid];
#pragma unroll
                for (int k = 0; k < 4; ++k) v += s.ws[k*768 + tid];
                s.qkv[tid] = v;
                if (tid >= 256 && tid < 512) {
                    float sq = v * v;
#pragma unroll
                    for (int o = 16; o; o >>= 1)
                        sq += __shfl_xor_sync(0xffffffffu, sq, o);
                    if ((tid & 31) == 0) s.kssq[(tid - 256) >> 5] = sq;
                }
            }
            __syncthreads();
            // state update + o (S in registers; knorm folded in)
            {
                float4* Sreg = (l == 0) ? S0 : S1;
                const float ssq = s.kssq[2*hh_r] + s.kssq[2*hh_r + 1];
                const float knorm = 1.f / (sqrtf(ssq) + 1e-6f);
                const float betah = s.beta[hh_r];
                const int kb = hh_r*64 + part*16;
                float4 kkr[4];
#pragma unroll
                for (int g = 0; g < 4; ++g) {
                    float4 kraw = *(const float4*)&s.qkv[256 + kb + g*4];
                    kkr[g].x = kraw.x * knorm; kkr[g].y = kraw.y * knorm;
                    kkr[g].z = kraw.z * knorm; kkr[g].w = kraw.w * knorm;
                }
                float sk = 0.f;
#pragma unroll
                for (int g = 0; g < 4; ++g) {
                    sk += Sreg[g].x*kkr[g].x + Sreg[g].y*kkr[g].y
                        + Sreg[g].z*kkr[g].z + Sreg[g].w*kkr[g].w;
                }
                sk += __shfl_xor_sync(0xffffffffu, sk, 1);
                sk += __shfl_xor_sync(0xffffffffu, sk, 2);
                const float vh = s.qkv[512 + r_row];
                const float delta = betah * (vh - sk);
                float op = 0.f;
#pragma unroll
                for (int g = 0; g < 4; ++g) {
                    const float4 qq = *(const float4*)&s.qkv[kb + g*4];
                    Sreg[g].x += delta*kkr[g].x; Sreg[g].y += delta*kkr[g].y;
                    Sreg[g].z += delta*kkr[g].z; Sreg[g].w += delta*kkr[g].w;
                    op += Sreg[g].x*qq.x + Sreg[g].y*qq.y + Sreg[g].z*qq.z + Sreg[g].w*qq.w;
                }
                op += __shfl_xor_sync(0xffffffffu, op, 1);
                op += __shfl_xor_sync(0xffffffffu, op, 2);
                if (part == 0) s.ovec[r_row] = op;
            }
            __syncthreads();
            // pre = xh + o @ dn_wo + bo (f32x2); xh = LN(pre)
            {
                const int cg = tid & 63, ks = tid >> 6;
                const ulonglong2* W = (const ulonglong2*)(dn_wo + (size_t)l*HH*HH);
                unsigned long long a01 = 0ull, a23 = 0ull;
#pragma unroll 4
                for (int k = 0; k < 16; ++k) {
                    const int i = ks*16 + k;
                    const unsigned long long ov2 = bcast_f32x2(s.ovec[i]);
                    const ulonglong2 w = W[i*64 + cg];
                    fma_f32x2(a01, ov2, w.x);
                    fma_f32x2(a23, ov2, w.y);
                }
                ulonglong2 outv; outv.x = a01; outv.y = a23;
                *(ulonglong2*)&s.ws[ks*256 + cg*4] = outv;
            }
            __syncthreads();
            if (tid < 256) {
                float v = s.xh[tid] + (&s.c_bo[0][0])[l*256 + tid];
#pragma unroll
                for (int k = 0; k < 16; ++k) v += s.ws[k*256 + tid];
                s.pre[tid] = v;
            }
            __syncthreads();
            if (tid < 32) {
                float sum = 0.f, sq = 0.f;
#pragma unroll
                for (int e = 0; e < 8; ++e) {
                    const float v = s.pre[tid + 32*e];
                    sum += v; sq += v*v;
                }
#pragma unroll
                for (int o = 16; o; o >>= 1) {
                    sum += __shfl_xor_sync(0xffffffffu, sum, o);
                    sq  += __shfl_xor_sync(0xffffffffu, sq,  o);
                }
                if (tid == 0) {
                    const float mean = sum * (1.f/256.f);
                    const float var  = sq * (1.f/256.f) - mean*mean;
                    s.red2[0] = mean;
                    s.red2[1] = rsqrtf(var + 1e-5f);
                }
            }
            __syncthreads();
            if (tid < 256) {
                s.xh[tid] = (s.pre[tid] - s.red2[0]) * s.red2[1]
                          * (&s.c_lng[0][0])[l*256 + tid] + (&s.c_lnb[0][0])[l*256 + tid];
            }
            __syncthreads();
        }

        // ---- sup projection: proj = xh @ sup_w (f32x2) ----
        {
            const int cg = tid & 31, ks = tid >> 5;
            const ulonglong2* W = (const ulonglong2*)sup_w;
            unsigned long long a01 = 0ull, a23 = 0ull;
#pragma unroll
            for (int k = 0; k < 8; ++k) {
                const int i = ks*8 + k;
                const unsigned long long xv2 = bcast_f32x2(s.xh[i]);
                const ulonglong2 w = W[i*32 + cg];
                fma_f32x2(a01, xv2, w.x);
                fma_f32x2(a23, xv2, w.y);
            }
            ulonglong2 outv; outv.x = a01; outv.y = a23;
            *(ulonglong2*)&s.ws[ks*128 + cg*4] = outv;
        }
        __syncthreads();
        if (tid < 128) {
            float v = 0.f;
#pragma unroll
            for (int k = 0; k < 32; ++k) v += s.ws[k*128 + tid];
            s.proj[tid] = v;
        } else if (tid >= 256 && tid < 512) {
            g_xh[idx*HH + (tid - 256)] = s.xh[tid - 256];
        }
        __syncthreads();

        // ---- prefetch next token's vectors ----
        if (t + 1 < SS) {
            const size_t idx1 = idx + 1;
            if (tid < 32)       pv = ((const float4*)(g_q  + idx1*SDIM))[tid];
            else if (tid < 64)  pv = ((const float4*)(g_wr + idx1*SDIM))[tid-32];
            else if (tid < 80)  pv = ((const float4*)(g_ba + idx1*NSLOT))[tid-64];
        }

        // ---- second gated slot write ----
        {
            const int col = tid & 127, grp = tid >> 7;
            const float pvv = s.proj[col], sbv = s.c_supb[col];
#pragma unroll
            for (int k = 0; k < 8; ++k) {
                const int n = grp*8 + k;
                const float gn = s.g2[n];
                const float sv = s.ba[n]*pvv + sbv;
                const float oldv = s.slots[n][col];
                s.slots[n][col] = oldv + gn*(sv - oldv);
            }
        }
        __syncthreads();
    }
}

// ============================================================================
extern "C" void kernel_launch(void* const* d_in, const int* in_sizes, int n_in,
                              void* d_out, int out_size) {
    (void)in_sizes; (void)n_in; (void)out_size;
    const float* x        = (const float*)d_in[0];
    const float* sb_init  = (const float*)d_in[1];
    const float* sb_wq    = (const float*)d_in[2];
    const float* sb_bq    = (const float*)d_in[3];
    const float* sb_ww    = (const float*)d_in[4];
    const float* sb_bw    = (const float*)d_in[5];
    const float* sb_wo    = (const float*)d_in[6];
    const float* sb_bo    = (const float*)d_in[7];
    const float* p_win    = (const float*)d_in[8];
    const float* p_bin    = (const float*)d_in[9];
    const float* b_wq     = (const float*)d_in[10];
    const float* b_bq     = (const float*)d_in[11];
    const float* b_keys   = (const float*)d_in[12];
    const float* bp_w     = (const float*)d_in[13];
    const float* bp_b     = (const float*)d_in[14];
    const float* dn_wqkv  = (const float*)d_in[15];
    const float* dn_bqkv  = (const float*)d_in[16];
    const float* dn_wbeta = (const float*)d_in[17];
    const float* dn_bbeta = (const float*)d_in[18];
    const float* dn_wo    = (const float*)d_in[19];
    const float* dn_bo    = (const float*)d_in[20];
    const float* dn_lng   = (const float*)d_in[21];
    const float* dn_lnb   = (const float*)d_in[22];
    const float* sup_w    = (const float*)d_in[23];
    const float* sup_b    = (const float*)d_in[24];
    const float* op_w     = (const float*)d_in[25];
    const float* op_b     = (const float*)d_in[26];
    const float* oln_g    = (const float*)d_in[27];
    const float* oln_b    = (const float*)d_in[28];
    const float* ow       = (const float*)d_in[29];
    const float* ob       = (const float*)d_in[30];
    float* out = (float*)d_out;

    float *gq, *gwr, *gxh0, *gbq, *gba, *gread, *gxh, *gypre, *glnx;
    cudaGetSymbolAddress((void**)&gq,    g_q);
    cudaGetSymbolAddress((void**)&gwr,   g_wr);
    cudaGetSymbolAddress((void**)&gxh0,  g_xh0);
    cudaGetSymbolAddress((void**)&gbq,   g_bq);
    cudaGetSymbolAddress((void**)&gba,   g_ba);
    cudaGetSymbolAddress((void**)&gread, g_read);
    cudaGetSymbolAddress((void**)&gxh,   g_xh);
    cudaGetSymbolAddress((void**)&gypre, g_ypre);
    cudaGetSymbolAddress((void**)&glnx,  g_lnx);

    const int seq_smem = (int)sizeof(SeqSmem);
    cudaFuncSetAttribute(seq_kernel, cudaFuncAttributeMaxDynamicSharedMemorySize, seq_smem);

    dim3 blk(256);
    // precompute phase
    gemm_bias<<<dim3(SDIM/64, TOK/64), blk>>>(x, sb_wq, sb_bq, gq,   TOK, SDIM, DD, 0);
    gemm_bias<<<dim3(SDIM/64, TOK/64), blk>>>(x, sb_ww, sb_bw, gwr,  TOK, SDIM, DD, 0);
    gemm_bias<<<dim3(HH/64,   TOK/64), blk>>>(x, p_win, p_bin, gxh0, TOK, HH,   DD, 0);
    gemm_bias<<<dim3(SDIM/64, TOK/64), blk>>>(gxh0, b_wq, b_bq, gbq, TOK, SDIM, HH, 0);
    ba_kernel<<<TOK, 64>>>(gbq, b_keys, gba);

    // sequential core
    seq_kernel<<<BB, 1024, seq_smem>>>(sb_init, bp_w, bp_b,
                                       dn_wqkv, dn_bqkv, dn_wbeta, dn_bbeta,
                                       dn_wo, dn_bo, dn_lng, dn_lnb,
                                       sup_w, sup_b);

    // deferred output projections
    gemm_bias<<<dim3(DD/64, TOK/64), blk>>>(gread, sb_wo, sb_bo, gypre, TOK, DD, SDIM, 0);
    gemm_bias<<<dim3(DD/64, TOK/64), blk>>>(gxh,   op_w,  op_b,  gypre, TOK, DD, HH,   1);
    ln512_kernel<<<TOK, 256>>>(gypre, oln_g, oln_b, glnx);
    gemm_bias<<<dim3(DD/64, TOK/64), blk>>>(glnx, ow, ob, out, TOK, DD, DD, 0);
}